// round 11
// baseline (speedup 1.0000x reference)
#include <cuda_runtime.h>
#include <cuda_fp16.h>
#include <cuda_bf16.h>
#include <cstdint>
#include <cstddef>

#define MDIM 8192
#define KDIM 4096
#define NDIM 4096
#define NBLK 32            // K blocks of 128 for weight scales
#define NTILES_N (NDIM / 64)            // 64
#define NTILES   ((MDIM / 128) * NTILES_N)  // 4096
#define GRID_P 304                      // 2 CTAs/SM x 152 SMs (GB300)

// ---------------- static device scratch ----------------
__device__ __align__(1024) signed char g_xq[(size_t)MDIM * KDIM];  // int8 activations
__device__ __align__(1024) signed char g_wq[(size_t)NDIM * KDIM];  // int8 weights (packed from int32 input)
__device__ float g_xs[MDIM];                                        // per-row activation scales

// ---------------- helpers ----------------
__device__ __forceinline__ uint32_t smem_u32(const void* p) {
    uint32_t a;
    asm("{ .reg .u64 t; cvta.to.shared.u64 t, %1; cvt.u32.u64 %0, t; }" : "=r"(a) : "l"(p));
    return a;
}
__device__ __forceinline__ void cp_async16(uint32_t dst_smem, const void* src) {
    asm volatile("cp.async.cg.shared.global [%0], [%1], 16;" :: "r"(dst_smem), "l"(src) : "memory");
}
__device__ __forceinline__ void cp_commit() {
    asm volatile("cp.async.commit_group;" ::: "memory");
}
__device__ __forceinline__ void ldsm_x4(uint32_t* r, uint32_t addr) {
    asm volatile("ldmatrix.sync.aligned.m8n8.x4.shared.b16 {%0,%1,%2,%3}, [%4];"
        : "=r"(r[0]), "=r"(r[1]), "=r"(r[2]), "=r"(r[3]) : "r"(addr));
}
__device__ __forceinline__ void imma16832(int* d, const uint32_t* a, uint32_t b0, uint32_t b1) {
    asm volatile("mma.sync.aligned.m16n8k32.row.col.s32.s8.s8.s32 "
        "{%0,%1,%2,%3}, {%4,%5,%6,%7}, {%8,%9}, {%0,%1,%2,%3};"
        : "+r"(d[0]), "+r"(d[1]), "+r"(d[2]), "+r"(d[3])
        : "r"(a[0]), "r"(a[1]), "r"(a[2]), "r"(a[3]), "r"(b0), "r"(b1));
}

// ---------------- kernel 1: fused prep (quant x rows | pack weight rows) ----------------
__global__ void __launch_bounds__(256) prep_kernel(const float* __restrict__ x,
                                                   const int* __restrict__ wq32) {
    const int t = threadIdx.x;
    if (blockIdx.x >= MDIM) {
        const int r = blockIdx.x - MDIM;
        const int4* src = reinterpret_cast<const int4*>(wq32 + (size_t)r * KDIM);
        char4* dst = reinterpret_cast<char4*>(g_wq + (size_t)r * KDIM);
#pragma unroll
        for (int i = 0; i < 4; i++) {
            int idx = t + 256 * i;
            int4 v = src[idx];
            char4 c;
            c.x = (signed char)v.x; c.y = (signed char)v.y;
            c.z = (signed char)v.z; c.w = (signed char)v.w;
            dst[idx] = c;
        }
        return;
    }
    const int row = blockIdx.x;
    const float4* xr = reinterpret_cast<const float4*>(x) + (size_t)row * (KDIM / 4);
    float4 v[4];
    float amax = 0.f;
#pragma unroll
    for (int i = 0; i < 4; i++) {
        v[i] = xr[t + 256 * i];
        amax = fmaxf(amax, fmaxf(fmaxf(fabsf(v[i].x), fabsf(v[i].y)), fmaxf(fabsf(v[i].z), fabsf(v[i].w))));
    }
#pragma unroll
    for (int o = 16; o; o >>= 1) amax = fmaxf(amax, __shfl_xor_sync(0xffffffffu, amax, o));
    __shared__ float warpmax[8];
    __shared__ float s_scale;
    if ((t & 31) == 0) warpmax[t >> 5] = amax;
    __syncthreads();
    if (t == 0) {
        float m = warpmax[0];
#pragma unroll
        for (int i = 1; i < 8; i++) m = fmaxf(m, warpmax[i]);
        float s = fmaxf(m, 1e-6f) / 127.0f;
        g_xs[row] = s;
        s_scale = s;
    }
    __syncthreads();
    const float s = s_scale;
    char4* orow = reinterpret_cast<char4*>(g_xq + (size_t)row * KDIM);
#pragma unroll
    for (int i = 0; i < 4; i++) {
        int idx = t + 256 * i;
        char4 c;
        c.x = (signed char)max(-128, min(127, __float2int_rn(v[i].x / s)));
        c.y = (signed char)max(-128, min(127, __float2int_rn(v[i].y / s)));
        c.z = (signed char)max(-128, min(127, __float2int_rn(v[i].z / s)));
        c.w = (signed char)max(-128, min(127, __float2int_rn(v[i].w / s)));
        orow[idx] = c;
    }
}

// ---------------- kernel 2: persistent int8 GEMM, CTA 128(M)x64(N), 2 CTAs/SM ----------------
// 8 warps: wm = wid&3 (M offset 32*wm), wn = wid>>2 (N offset 32*wn). Warp tile 32x32.
// SMEM rows padded to 144B for conflict-free ldmatrix. Weight scales via __ldg (L2-resident).
// Persistent: each CTA loops tiles with stride gridDim.x; next tile's prologue cp.asyncs
// are issued BEFORE the epilogue so the fill hides behind epilogue math + stores.

#define ROWB 144
#define TILE_A_BYTES (128 * ROWB)          // 18432
#define TILE_B_BYTES (64 * ROWB)           // 9216
#define STAGE_BYTES (TILE_A_BYTES + TILE_B_BYTES)   // 27648
#define STAGES 4
#define SMEM_DYN (STAGES * STAGE_BYTES)    // 110592 -> 2 CTAs/SM

__device__ __forceinline__ void load_stage(uint32_t sbase, const signed char* gA,
                                           const signed char* gB, int blk, int tid) {
    const int koff = blk * 128;
#pragma unroll
    for (int i = 0; i < 4; i++) {            // A: 1024 x 16B chunks, 256 threads
        int idx = tid + i * 256;
        int r = idx >> 3, c = idx & 7;
        cp_async16(sbase + (uint32_t)r * ROWB + (uint32_t)(c << 4),
                   gA + (size_t)r * KDIM + koff + c * 16);
    }
    uint32_t bb = sbase + TILE_A_BYTES;
#pragma unroll
    for (int i = 0; i < 2; i++) {            // B: 512 x 16B chunks
        int idx = tid + i * 256;
        int r = idx >> 3, c = idx & 7;
        cp_async16(bb + (uint32_t)r * ROWB + (uint32_t)(c << 4),
                   gB + (size_t)r * KDIM + koff + c * 16);
    }
}

__global__ void __launch_bounds__(256, 2) gemm_kernel(const float* __restrict__ ws,
                                                      const float* __restrict__ bias,
                                                      float* __restrict__ out) {
    extern __shared__ char dsm[];

    const int tid = threadIdx.x;
    const int wid = tid >> 5;
    const int lane = tid & 31;
    const int wm = wid & 3;                  // M offset 32*wm
    const int wn = wid >> 2;                 // N offset 32*wn (0..1)
    const uint32_t sbase0 = smem_u32(dsm);

    // ldmatrix base offsets (within a stage)
    const uint32_t a_lrow = (uint32_t)(wm * 32 + (lane & 15)) * ROWB + (uint32_t)(lane & 16);
    const uint32_t b_lrow = (uint32_t)(wn * 32 + (lane & 7) + ((lane & 16) >> 1)) * ROWB
                          + (uint32_t)((lane & 8) << 1);

    int t = blockIdx.x;
    int m0 = (t >> 6) * 128;
    int n0 = (t & 63) * 64;
    const signed char* gA = g_xq + (size_t)m0 * KDIM;
    const signed char* gB = g_wq + (size_t)n0 * KDIM;

    // first tile prologue: fill 3 stages
#pragma unroll
    for (int s = 0; s < 3; s++) {
        load_stage(sbase0 + s * STAGE_BYTES, gA, gB, s, tid);
        cp_commit();
    }

    while (true) {
        const float* wsp = ws + n0 + wn * 32 + (lane & 3) * 2;

        float facc[2][4][4];
#pragma unroll
        for (int mt = 0; mt < 2; mt++)
#pragma unroll
            for (int nt = 0; nt < 4; nt++)
#pragma unroll
                for (int r = 0; r < 4; r++) facc[mt][nt][r] = 0.f;

        for (int blk = 0; blk < NBLK; blk++) {
            asm volatile("cp.async.wait_group 2;" ::: "memory");
            __syncthreads();   // stage blk visible everywhere; stage blk-1 free

            if (blk + 3 < NBLK)
                load_stage(sbase0 + ((blk + 3) & 3) * STAGE_BYTES, gA, gB, blk + 3, tid);
            cp_commit();

            const uint32_t abase = sbase0 + (blk & 3) * STAGE_BYTES;
            const uint32_t bbase = abase + TILE_A_BYTES;

            int ci[2][4][4];
#pragma unroll
            for (int mt = 0; mt < 2; mt++)
#pragma unroll
                for (int nt = 0; nt < 4; nt++)
#pragma unroll
                    for (int r = 0; r < 4; r++) ci[mt][nt][r] = 0;

#pragma unroll
            for (int ks = 0; ks < 4; ks++) {
                const uint32_t kb = ks * 32;
                uint32_t af[2][4];
#pragma unroll
                for (int mt = 0; mt < 2; mt++)
                    ldsm_x4(af[mt], abase + a_lrow + (uint32_t)(mt * 16) * ROWB + kb);
                uint32_t bf[2][4];
#pragma unroll
                for (int g = 0; g < 2; g++)
                    ldsm_x4(bf[g], bbase + b_lrow + (uint32_t)(g * 16) * ROWB + kb);
#pragma unroll
                for (int mt = 0; mt < 2; mt++)
#pragma unroll
                    for (int nt = 0; nt < 4; nt++)
                        imma16832(ci[mt][nt], af[mt], bf[nt >> 1][(nt & 1) * 2],
                                  bf[nt >> 1][(nt & 1) * 2 + 1]);
            }

            // per-block fp32 fixup; scales straight from L2 (hot line, shared across CTAs)
            const float* wsb = wsp + (size_t)blk * NDIM;
#pragma unroll
            for (int nt = 0; nt < 4; nt++) {
                const float2 s2 = __ldg(reinterpret_cast<const float2*>(wsb + nt * 8));
#pragma unroll
                for (int mt = 0; mt < 2; mt++) {
                    facc[mt][nt][0] += (float)ci[mt][nt][0] * s2.x;
                    facc[mt][nt][1] += (float)ci[mt][nt][1] * s2.y;
                    facc[mt][nt][2] += (float)ci[mt][nt][2] * s2.x;
                    facc[mt][nt][3] += (float)ci[mt][nt][3] * s2.y;
                }
            }
        }

        // all warps done reading stages before next tile's loads overwrite them
        __syncthreads();

        const int tn = t + GRID_P;
        const bool more = tn < NTILES;
        if (more) {
            const int m0n = (tn >> 6) * 128;
            const int n0n = (tn & 63) * 64;
            const signed char* gAn = g_xq + (size_t)m0n * KDIM;
            const signed char* gBn = g_wq + (size_t)n0n * KDIM;
#pragma unroll
            for (int s = 0; s < 3; s++) {
                load_stage(sbase0 + s * STAGE_BYTES, gAn, gBn, s, tid);
                cp_commit();
            }
        }

        // ---------------- epilogue: * xs[row] + bias[col] (overlaps next-tile fill) ----------------
#pragma unroll
        for (int mt = 0; mt < 2; mt++) {
            const int r0 = m0 + wm * 32 + mt * 16 + (lane >> 2);
            const float xs0 = g_xs[r0];
            const float xs1 = g_xs[r0 + 8];
#pragma unroll
            for (int nt = 0; nt < 4; nt++) {
                const int col = n0 + wn * 32 + nt * 8 + (lane & 3) * 2;
                const float2 b2 = *reinterpret_cast<const float2*>(bias + col);
                float2 o0, o1;
                o0.x = facc[mt][nt][0] * xs0 + b2.x;
                o0.y = facc[mt][nt][1] * xs0 + b2.y;
                o1.x = facc[mt][nt][2] * xs1 + b2.x;
                o1.y = facc[mt][nt][3] * xs1 + b2.y;
                *reinterpret_cast<float2*>(out + (size_t)r0 * NDIM + col) = o0;
                *reinterpret_cast<float2*>(out + (size_t)(r0 + 8) * NDIM + col) = o1;
            }
        }

        if (!more) break;
        t = tn;
        m0 = (t >> 6) * 128;
        n0 = (t & 63) * 64;
        gA = g_xq + (size_t)m0 * KDIM;
        gB = g_wq + (size_t)n0 * KDIM;
    }
}

// ---------------- launch: inputs identified BY SIZE (order-proof) ----------------
extern "C" void kernel_launch(void* const* d_in, const int* in_sizes, int n_in,
                              void* d_out, int out_size) {
    const float* x = nullptr;          // 33554432 elems (float32)
    const int* wq32 = nullptr;         // 16777216 elems (int8 sign-extended to int32)
    const float* ws = nullptr;         // 131072 elems (float32)
    const float* bias = nullptr;       // 4096 elems (float32)
    for (int i = 0; i < n_in; i++) {
        long long sz = in_sizes[i];
        if (sz == (long long)MDIM * KDIM)      x = (const float*)d_in[i];
        else if (sz == (long long)NDIM * KDIM) wq32 = (const int*)d_in[i];
        else if (sz == (long long)NBLK * NDIM) ws = (const float*)d_in[i];
        else if (sz == NDIM)                   bias = (const float*)d_in[i];
    }
    float* out = (float*)d_out;

    cudaFuncSetAttribute(gemm_kernel, cudaFuncAttributeMaxDynamicSharedMemorySize, SMEM_DYN);

    prep_kernel<<<MDIM + NDIM, 256>>>(x, wq32);
    gemm_kernel<<<GRID_P, 256, SMEM_DYN>>>(ws, bias, out);
}

// round 13
// speedup vs baseline: 1.0984x; 1.0984x over previous
#include <cuda_runtime.h>
#include <cuda_fp16.h>
#include <cuda_bf16.h>
#include <cstdint>
#include <cstddef>

#define MDIM 8192
#define KDIM 4096
#define NDIM 4096
#define NBLK 32            // K blocks of 128 for weight scales

// ---------------- static device scratch ----------------
__device__ __align__(1024) signed char g_xq[(size_t)MDIM * KDIM];  // int8 activations
__device__ __align__(1024) signed char g_wq[(size_t)NDIM * KDIM];  // int8 weights (packed from int32 input)
__device__ float g_xs[MDIM];                                        // per-row activation scales

// ---------------- helpers ----------------
__device__ __forceinline__ uint32_t smem_u32(const void* p) {
    uint32_t a;
    asm("{ .reg .u64 t; cvta.to.shared.u64 t, %1; cvt.u32.u64 %0, t; }" : "=r"(a) : "l"(p));
    return a;
}
__device__ __forceinline__ void cp_async16(uint32_t dst_smem, const void* src) {
    asm volatile("cp.async.cg.shared.global [%0], [%1], 16;" :: "r"(dst_smem), "l"(src) : "memory");
}
__device__ __forceinline__ void cp_commit() {
    asm volatile("cp.async.commit_group;" ::: "memory");
}
__device__ __forceinline__ void ldsm_x4(uint32_t* r, uint32_t addr) {
    asm volatile("ldmatrix.sync.aligned.m8n8.x4.shared.b16 {%0,%1,%2,%3}, [%4];"
        : "=r"(r[0]), "=r"(r[1]), "=r"(r[2]), "=r"(r[3]) : "r"(addr));
}
__device__ __forceinline__ void imma16832(int* d, const uint32_t* a, uint32_t b0, uint32_t b1) {
    asm volatile("mma.sync.aligned.m16n8k32.row.col.s32.s8.s8.s32 "
        "{%0,%1,%2,%3}, {%4,%5,%6,%7}, {%8,%9}, {%0,%1,%2,%3};"
        : "+r"(d[0]), "+r"(d[1]), "+r"(d[2]), "+r"(d[3])
        : "r"(a[0]), "r"(a[1]), "r"(a[2]), "r"(a[3]), "r"(b0), "r"(b1));
}
__device__ __forceinline__ void stg_cs_f2(float* p, float2 v) {
    asm volatile("st.global.cs.v2.f32 [%0], {%1, %2};" :: "l"(p), "f"(v.x), "f"(v.y) : "memory");
}

// ---------------- kernel 1: fused prep (quant x rows | pack weight rows) ----------------
__global__ void __launch_bounds__(256) prep_kernel(const float* __restrict__ x,
                                                   const int* __restrict__ wq32) {
    const int t = threadIdx.x;
    if (blockIdx.x >= MDIM) {
        const int r = blockIdx.x - MDIM;
        const int4* src = reinterpret_cast<const int4*>(wq32 + (size_t)r * KDIM);
        char4* dst = reinterpret_cast<char4*>(g_wq + (size_t)r * KDIM);
#pragma unroll
        for (int i = 0; i < 4; i++) {
            int idx = t + 256 * i;
            int4 v = src[idx];
            char4 c;
            c.x = (signed char)v.x; c.y = (signed char)v.y;
            c.z = (signed char)v.z; c.w = (signed char)v.w;
            dst[idx] = c;
        }
        return;
    }
    const int row = blockIdx.x;
    const float4* xr = reinterpret_cast<const float4*>(x) + (size_t)row * (KDIM / 4);
    float4 v[4];
    float amax = 0.f;
#pragma unroll
    for (int i = 0; i < 4; i++) {
        v[i] = xr[t + 256 * i];
        amax = fmaxf(amax, fmaxf(fmaxf(fabsf(v[i].x), fabsf(v[i].y)), fmaxf(fabsf(v[i].z), fabsf(v[i].w))));
    }
#pragma unroll
    for (int o = 16; o; o >>= 1) amax = fmaxf(amax, __shfl_xor_sync(0xffffffffu, amax, o));
    __shared__ float warpmax[8];
    __shared__ float s_scale;
    if ((t & 31) == 0) warpmax[t >> 5] = amax;
    __syncthreads();
    if (t == 0) {
        float m = warpmax[0];
#pragma unroll
        for (int i = 1; i < 8; i++) m = fmaxf(m, warpmax[i]);
        float s = fmaxf(m, 1e-6f) / 127.0f;
        g_xs[row] = s;
        s_scale = s;
    }
    __syncthreads();
    const float s = s_scale;
    char4* orow = reinterpret_cast<char4*>(g_xq + (size_t)row * KDIM);
#pragma unroll
    for (int i = 0; i < 4; i++) {
        int idx = t + 256 * i;
        char4 c;
        c.x = (signed char)max(-128, min(127, __float2int_rn(v[i].x / s)));
        c.y = (signed char)max(-128, min(127, __float2int_rn(v[i].y / s)));
        c.z = (signed char)max(-128, min(127, __float2int_rn(v[i].z / s)));
        c.w = (signed char)max(-128, min(127, __float2int_rn(v[i].w / s)));
        orow[idx] = c;
    }
}

// ---------------- kernel 2: int8 GEMM, CTA 128(M)x64(N), 256 thr, 2 CTAs/SM ----------------
// 8 warps: wm = wid&3 (M offset 32*wm), wn = wid>>2 (N offset 32*wn). Warp tile 32x32.
// SMEM rows padded to 144B for conflict-free ldmatrix. Weight scales via __ldg (L2-resident).

#define ROWB 144
#define TILE_A_BYTES (128 * ROWB)          // 18432
#define TILE_B_BYTES (64 * ROWB)           // 9216
#define STAGE_BYTES (TILE_A_BYTES + TILE_B_BYTES)   // 27648
#define STAGES 4
#define SMEM_DYN (STAGES * STAGE_BYTES)    // 110592 -> 2 CTAs/SM

__device__ __forceinline__ void load_stage(uint32_t sbase, const signed char* gA,
                                           const signed char* gB, int blk, int tid) {
    const int koff = blk * 128;
#pragma unroll
    for (int i = 0; i < 4; i++) {            // A: 1024 x 16B chunks, 256 threads
        int idx = tid + i * 256;
        int r = idx >> 3, c = idx & 7;
        cp_async16(sbase + (uint32_t)r * ROWB + (uint32_t)(c << 4),
                   gA + (size_t)r * KDIM + koff + c * 16);
    }
    uint32_t bb = sbase + TILE_A_BYTES;
#pragma unroll
    for (int i = 0; i < 2; i++) {            // B: 512 x 16B chunks
        int idx = tid + i * 256;
        int r = idx >> 3, c = idx & 7;
        cp_async16(bb + (uint32_t)r * ROWB + (uint32_t)(c << 4),
                   gB + (size_t)r * KDIM + koff + c * 16);
    }
}

__global__ void __launch_bounds__(256, 2) gemm_kernel(const float* __restrict__ ws,
                                                      const float* __restrict__ bias,
                                                      float* __restrict__ out) {
    extern __shared__ char dsm[];

    const int tid = threadIdx.x;
    const int wid = tid >> 5;
    const int lane = tid & 31;
    const int wm = wid & 3;                  // M offset 32*wm
    const int wn = wid >> 2;                 // N offset 32*wn (0..1)
    const int m0 = blockIdx.y * 128;
    const int n0 = blockIdx.x * 64;
    const uint32_t sbase0 = smem_u32(dsm);

    const signed char* gA = g_xq + (size_t)m0 * KDIM;
    const signed char* gB = g_wq + (size_t)n0 * KDIM;

    float facc[2][4][4];
#pragma unroll
    for (int mt = 0; mt < 2; mt++)
#pragma unroll
        for (int nt = 0; nt < 4; nt++)
#pragma unroll
            for (int r = 0; r < 4; r++) facc[mt][nt][r] = 0.f;

    // prologue: fill 3 stages
#pragma unroll
    for (int s = 0; s < 3; s++) {
        load_stage(sbase0 + s * STAGE_BYTES, gA, gB, s, tid);
        cp_commit();
    }

    // ldmatrix base offsets (within a stage)
    const uint32_t a_lrow = (uint32_t)(wm * 32 + (lane & 15)) * ROWB + (uint32_t)(lane & 16);
    const uint32_t b_lrow = (uint32_t)(wn * 32 + (lane & 7) + ((lane & 16) >> 1)) * ROWB
                          + (uint32_t)((lane & 8) << 1);

    // per-thread weight-scale pointer: ws[blk*NDIM + col], col = n0 + wn*32 + nt*8 + (lane&3)*2
    const float* wsp = ws + n0 + wn * 32 + (lane & 3) * 2;

    for (int blk = 0; blk < NBLK; blk++) {
        asm volatile("cp.async.wait_group 2;" ::: "memory");
        __syncthreads();   // stage blk visible; all warps done with stage blk-1

        if (blk + 3 < NBLK)
            load_stage(sbase0 + ((blk + 3) & 3) * STAGE_BYTES, gA, gB, blk + 3, tid);
        cp_commit();

        const uint32_t abase = sbase0 + (blk & 3) * STAGE_BYTES;
        const uint32_t bbase = abase + TILE_A_BYTES;

        int ci[2][4][4];
#pragma unroll
        for (int mt = 0; mt < 2; mt++)
#pragma unroll
            for (int nt = 0; nt < 4; nt++)
#pragma unroll
                for (int r = 0; r < 4; r++) ci[mt][nt][r] = 0;

#pragma unroll
        for (int ks = 0; ks < 4; ks++) {
            const uint32_t kb = ks * 32;
            uint32_t af[2][4];
#pragma unroll
            for (int mt = 0; mt < 2; mt++)
                ldsm_x4(af[mt], abase + a_lrow + (uint32_t)(mt * 16) * ROWB + kb);
            uint32_t bf[2][4];
#pragma unroll
            for (int g = 0; g < 2; g++)
                ldsm_x4(bf[g], bbase + b_lrow + (uint32_t)(g * 16) * ROWB + kb);
#pragma unroll
            for (int mt = 0; mt < 2; mt++)
#pragma unroll
                for (int nt = 0; nt < 4; nt++)
                    imma16832(ci[mt][nt], af[mt], bf[nt >> 1][(nt & 1) * 2],
                              bf[nt >> 1][(nt & 1) * 2 + 1]);
        }

        // per-block fp32 fixup; scales straight from L2 (hot line, shared across CTAs)
        const float* wsb = wsp + (size_t)blk * NDIM;
#pragma unroll
        for (int nt = 0; nt < 4; nt++) {
            const float2 s2 = __ldg(reinterpret_cast<const float2*>(wsb + nt * 8));
#pragma unroll
            for (int mt = 0; mt < 2; mt++) {
                facc[mt][nt][0] += (float)ci[mt][nt][0] * s2.x;
                facc[mt][nt][1] += (float)ci[mt][nt][1] * s2.y;
                facc[mt][nt][2] += (float)ci[mt][nt][2] * s2.x;
                facc[mt][nt][3] += (float)ci[mt][nt][3] * s2.y;
            }
        }
    }

    // ---------------- epilogue: * xs[row] + bias[col]; streaming stores (st.cs) ----------------
#pragma unroll
    for (int mt = 0; mt < 2; mt++) {
        const int r0 = m0 + wm * 32 + mt * 16 + (lane >> 2);
        const float xs0 = g_xs[r0];
        const float xs1 = g_xs[r0 + 8];
#pragma unroll
        for (int nt = 0; nt < 4; nt++) {
            const int col = n0 + wn * 32 + nt * 8 + (lane & 3) * 2;
            const float2 b2 = __ldg(reinterpret_cast<const float2*>(bias + col));
            float2 o0, o1;
            o0.x = facc[mt][nt][0] * xs0 + b2.x;
            o0.y = facc[mt][nt][1] * xs0 + b2.y;
            o1.x = facc[mt][nt][2] * xs1 + b2.x;
            o1.y = facc[mt][nt][3] * xs1 + b2.y;
            stg_cs_f2(out + (size_t)r0 * NDIM + col, o0);
            stg_cs_f2(out + (size_t)(r0 + 8) * NDIM + col, o1);
        }
    }
}

// ---------------- launch: inputs identified BY SIZE (order-proof) ----------------
extern "C" void kernel_launch(void* const* d_in, const int* in_sizes, int n_in,
                              void* d_out, int out_size) {
    const float* x = nullptr;          // 33554432 elems (float32)
    const int* wq32 = nullptr;         // 16777216 elems (int8 sign-extended to int32)
    const float* ws = nullptr;         // 131072 elems (float32)
    const float* bias = nullptr;       // 4096 elems (float32)
    for (int i = 0; i < n_in; i++) {
        long long sz = in_sizes[i];
        if (sz == (long long)MDIM * KDIM)      x = (const float*)d_in[i];
        else if (sz == (long long)NDIM * KDIM) wq32 = (const int*)d_in[i];
        else if (sz == (long long)NBLK * NDIM) ws = (const float*)d_in[i];
        else if (sz == NDIM)                   bias = (const float*)d_in[i];
    }
    float* out = (float*)d_out;

    cudaFuncSetAttribute(gemm_kernel, cudaFuncAttributeMaxDynamicSharedMemorySize, SMEM_DYN);

    prep_kernel<<<MDIM + NDIM, 256>>>(x, wq32);
    gemm_kernel<<<dim3(NDIM / 64, MDIM / 128, 1), 256, SMEM_DYN>>>(ws, bias, out);
}

// round 14
// speedup vs baseline: 1.1148x; 1.0150x over previous
#include <cuda_runtime.h>
#include <cuda_fp16.h>
#include <cuda_bf16.h>
#include <cstdint>
#include <cstddef>

#define MDIM 8192
#define KDIM 4096
#define NDIM 4096
#define NBLK 32            // K blocks of 128 for weight scales

// ---------------- static device scratch ----------------
__device__ __align__(1024) signed char g_xq[(size_t)MDIM * KDIM];  // int8 activations
__device__ __align__(1024) signed char g_wq[(size_t)NDIM * KDIM];  // int8 weights (packed from int32 input)
__device__ float g_xs[MDIM];                                        // per-row activation scales

// ---------------- helpers ----------------
__device__ __forceinline__ uint32_t smem_u32(const void* p) {
    uint32_t a;
    asm("{ .reg .u64 t; cvta.to.shared.u64 t, %1; cvt.u32.u64 %0, t; }" : "=r"(a) : "l"(p));
    return a;
}
__device__ __forceinline__ void cp_async16(uint32_t dst_smem, const void* src) {
    asm volatile("cp.async.cg.shared.global [%0], [%1], 16;" :: "r"(dst_smem), "l"(src) : "memory");
}
__device__ __forceinline__ void cp_commit() {
    asm volatile("cp.async.commit_group;" ::: "memory");
}
__device__ __forceinline__ void ldsm_x4(uint32_t* r, uint32_t addr) {
    asm volatile("ldmatrix.sync.aligned.m8n8.x4.shared.b16 {%0,%1,%2,%3}, [%4];"
        : "=r"(r[0]), "=r"(r[1]), "=r"(r[2]), "=r"(r[3]) : "r"(addr));
}
__device__ __forceinline__ void imma16832(int* d, const uint32_t* a, uint32_t b0, uint32_t b1) {
    asm volatile("mma.sync.aligned.m16n8k32.row.col.s32.s8.s8.s32 "
        "{%0,%1,%2,%3}, {%4,%5,%6,%7}, {%8,%9}, {%0,%1,%2,%3};"
        : "+r"(d[0]), "+r"(d[1]), "+r"(d[2]), "+r"(d[3])
        : "r"(a[0]), "r"(a[1]), "r"(a[2]), "r"(a[3]), "r"(b0), "r"(b1));
}
__device__ __forceinline__ void stg_cs_f2(float* p, float2 v) {
    asm volatile("st.global.cs.v2.f32 [%0], {%1, %2};" :: "l"(p), "f"(v.x), "f"(v.y) : "memory");
}

// ---------------- kernel 1: fused prep (quant x rows | pack weight rows) ----------------
__global__ void __launch_bounds__(256) prep_kernel(const float* __restrict__ x,
                                                   const int* __restrict__ wq32) {
    const int t = threadIdx.x;
    if (blockIdx.x >= MDIM) {
        const int r = blockIdx.x - MDIM;
        const int4* src = reinterpret_cast<const int4*>(wq32 + (size_t)r * KDIM);
        char4* dst = reinterpret_cast<char4*>(g_wq + (size_t)r * KDIM);
#pragma unroll
        for (int i = 0; i < 4; i++) {
            int idx = t + 256 * i;
            int4 v = src[idx];
            char4 c;
            c.x = (signed char)v.x; c.y = (signed char)v.y;
            c.z = (signed char)v.z; c.w = (signed char)v.w;
            dst[idx] = c;
        }
        return;
    }
    const int row = blockIdx.x;
    const float4* xr = reinterpret_cast<const float4*>(x) + (size_t)row * (KDIM / 4);
    float4 v[4];
    float amax = 0.f;
#pragma unroll
    for (int i = 0; i < 4; i++) {
        v[i] = xr[t + 256 * i];
        amax = fmaxf(amax, fmaxf(fmaxf(fabsf(v[i].x), fabsf(v[i].y)), fmaxf(fabsf(v[i].z), fabsf(v[i].w))));
    }
#pragma unroll
    for (int o = 16; o; o >>= 1) amax = fmaxf(amax, __shfl_xor_sync(0xffffffffu, amax, o));
    __shared__ float warpmax[8];
    __shared__ float s_scale;
    if ((t & 31) == 0) warpmax[t >> 5] = amax;
    __syncthreads();
    if (t == 0) {
        float m = warpmax[0];
#pragma unroll
        for (int i = 1; i < 8; i++) m = fmaxf(m, warpmax[i]);
        float s = fmaxf(m, 1e-6f) / 127.0f;
        g_xs[row] = s;
        s_scale = s;
    }
    __syncthreads();
    const float s = s_scale;
    char4* orow = reinterpret_cast<char4*>(g_xq + (size_t)row * KDIM);
#pragma unroll
    for (int i = 0; i < 4; i++) {
        int idx = t + 256 * i;
        char4 c;
        c.x = (signed char)max(-128, min(127, __float2int_rn(v[i].x / s)));
        c.y = (signed char)max(-128, min(127, __float2int_rn(v[i].y / s)));
        c.z = (signed char)max(-128, min(127, __float2int_rn(v[i].z / s)));
        c.w = (signed char)max(-128, min(127, __float2int_rn(v[i].w / s)));
        orow[idx] = c;
    }
}

// ---------------- kernel 2: int8 GEMM, CTA 64(M)x64(N), 256 thr, 3 CTAs/SM ----------------
// 8 warps: wm = wid&1 (M offset 32*wm), wn = wid>>1 (N offset 16*wn). Warp tile 32x16.
// One B ldmatrix.x4 per k32 step covers n16 x k32 (frags 0,1 = rows0-7; 2,3 = rows8-15).
// SMEM rows padded to 144B for conflict-free ldmatrix. Weight scales via __ldg.

#define ROWB 144
#define TILE_A_BYTES (64 * ROWB)           // 9216
#define TILE_B_BYTES (64 * ROWB)           // 9216
#define STAGE_BYTES (TILE_A_BYTES + TILE_B_BYTES)   // 18432
#define STAGES 4
#define SMEM_DYN (STAGES * STAGE_BYTES)    // 73728 -> 3 CTAs/SM (216KB)

__device__ __forceinline__ void load_stage(uint32_t sbase, const signed char* gA,
                                           const signed char* gB, int blk, int tid) {
    const int koff = blk * 128;
#pragma unroll
    for (int i = 0; i < 2; i++) {            // A: 512 x 16B chunks, 256 threads
        int idx = tid + i * 256;
        int r = idx >> 3, c = idx & 7;
        cp_async16(sbase + (uint32_t)r * ROWB + (uint32_t)(c << 4),
                   gA + (size_t)r * KDIM + koff + c * 16);
    }
    uint32_t bb = sbase + TILE_A_BYTES;
#pragma unroll
    for (int i = 0; i < 2; i++) {            // B: 512 x 16B chunks
        int idx = tid + i * 256;
        int r = idx >> 3, c = idx & 7;
        cp_async16(bb + (uint32_t)r * ROWB + (uint32_t)(c << 4),
                   gB + (size_t)r * KDIM + koff + c * 16);
    }
}

__global__ void __launch_bounds__(256, 3) gemm_kernel(const float* __restrict__ ws,
                                                      const float* __restrict__ bias,
                                                      float* __restrict__ out) {
    extern __shared__ char dsm[];

    const int tid = threadIdx.x;
    const int wid = tid >> 5;
    const int lane = tid & 31;
    const int wm = wid & 1;                  // M offset 32*wm
    const int wn = wid >> 1;                 // N offset 16*wn (0..3)
    const int m0 = blockIdx.y * 64;
    const int n0 = blockIdx.x * 64;
    const uint32_t sbase0 = smem_u32(dsm);

    const signed char* gA = g_xq + (size_t)m0 * KDIM;
    const signed char* gB = g_wq + (size_t)n0 * KDIM;

    float facc[2][2][4];
#pragma unroll
    for (int mt = 0; mt < 2; mt++)
#pragma unroll
        for (int nt = 0; nt < 2; nt++)
#pragma unroll
            for (int r = 0; r < 4; r++) facc[mt][nt][r] = 0.f;

    // prologue: fill 3 stages
#pragma unroll
    for (int s = 0; s < 3; s++) {
        load_stage(sbase0 + s * STAGE_BYTES, gA, gB, s, tid);
        cp_commit();
    }

    // ldmatrix base offsets (within a stage)
    const uint32_t a_lrow = (uint32_t)(wm * 32 + (lane & 15)) * ROWB + (uint32_t)(lane & 16);
    // B: one x4 covers n16 x k32: rows wn*16 + (lane&7) (+8 via lane&16), k-halves via lane&8
    const uint32_t b_lrow = (uint32_t)(wn * 16 + (lane & 7) + ((lane & 16) >> 1)) * ROWB
                          + (uint32_t)((lane & 8) << 1);

    // per-thread weight-scale pointer: ws[blk*NDIM + col], col = n0 + wn*16 + nt*8 + (lane&3)*2
    const float* wsp = ws + n0 + wn * 16 + (lane & 3) * 2;

    for (int blk = 0; blk < NBLK; blk++) {
        asm volatile("cp.async.wait_group 2;" ::: "memory");
        __syncthreads();   // stage blk visible; all warps done with stage blk-1

        if (blk + 3 < NBLK)
            load_stage(sbase0 + ((blk + 3) & 3) * STAGE_BYTES, gA, gB, blk + 3, tid);
        cp_commit();

        const uint32_t abase = sbase0 + (blk & 3) * STAGE_BYTES;
        const uint32_t bbase = abase + TILE_A_BYTES;

        int ci[2][2][4];
#pragma unroll
        for (int mt = 0; mt < 2; mt++)
#pragma unroll
            for (int nt = 0; nt < 2; nt++)
#pragma unroll
                for (int r = 0; r < 4; r++) ci[mt][nt][r] = 0;

#pragma unroll
        for (int ks = 0; ks < 4; ks++) {
            const uint32_t kb = ks * 32;
            uint32_t af[2][4];
#pragma unroll
            for (int mt = 0; mt < 2; mt++)
                ldsm_x4(af[mt], abase + a_lrow + (uint32_t)(mt * 16) * ROWB + kb);
            uint32_t bf[4];
            ldsm_x4(bf, bbase + b_lrow + kb);
#pragma unroll
            for (int mt = 0; mt < 2; mt++)
#pragma unroll
                for (int nt = 0; nt < 2; nt++)
                    imma16832(ci[mt][nt], af[mt], bf[nt * 2], bf[nt * 2 + 1]);
        }

        // per-block fp32 fixup; scales straight from L2 (hot line, shared across CTAs)
        const float* wsb = wsp + (size_t)blk * NDIM;
#pragma unroll
        for (int nt = 0; nt < 2; nt++) {
            const float2 s2 = __ldg(reinterpret_cast<const float2*>(wsb + nt * 8));
#pragma unroll
            for (int mt = 0; mt < 2; mt++) {
                facc[mt][nt][0] += (float)ci[mt][nt][0] * s2.x;
                facc[mt][nt][1] += (float)ci[mt][nt][1] * s2.y;
                facc[mt][nt][2] += (float)ci[mt][nt][2] * s2.x;
                facc[mt][nt][3] += (float)ci[mt][nt][3] * s2.y;
            }
        }
    }

    // ---------------- epilogue: * xs[row] + bias[col]; streaming stores ----------------
#pragma unroll
    for (int mt = 0; mt < 2; mt++) {
        const int r0 = m0 + wm * 32 + mt * 16 + (lane >> 2);
        const float xs0 = g_xs[r0];
        const float xs1 = g_xs[r0 + 8];
#pragma unroll
        for (int nt = 0; nt < 2; nt++) {
            const int col = n0 + wn * 16 + nt * 8 + (lane & 3) * 2;
            const float2 b2 = __ldg(reinterpret_cast<const float2*>(bias + col));
            float2 o0, o1;
            o0.x = facc[mt][nt][0] * xs0 + b2.x;
            o0.y = facc[mt][nt][1] * xs0 + b2.y;
            o1.x = facc[mt][nt][2] * xs1 + b2.x;
            o1.y = facc[mt][nt][3] * xs1 + b2.y;
            stg_cs_f2(out + (size_t)r0 * NDIM + col, o0);
            stg_cs_f2(out + (size_t)(r0 + 8) * NDIM + col, o1);
        }
    }
}

// ---------------- launch: inputs identified BY SIZE (order-proof) ----------------
extern "C" void kernel_launch(void* const* d_in, const int* in_sizes, int n_in,
                              void* d_out, int out_size) {
    const float* x = nullptr;          // 33554432 elems (float32)
    const int* wq32 = nullptr;         // 16777216 elems (int8 sign-extended to int32)
    const float* ws = nullptr;         // 131072 elems (float32)
    const float* bias = nullptr;       // 4096 elems (float32)
    for (int i = 0; i < n_in; i++) {
        long long sz = in_sizes[i];
        if (sz == (long long)MDIM * KDIM)      x = (const float*)d_in[i];
        else if (sz == (long long)NDIM * KDIM) wq32 = (const int*)d_in[i];
        else if (sz == (long long)NBLK * NDIM) ws = (const float*)d_in[i];
        else if (sz == NDIM)                   bias = (const float*)d_in[i];
    }
    float* out = (float*)d_out;

    cudaFuncSetAttribute(gemm_kernel, cudaFuncAttributeMaxDynamicSharedMemorySize, SMEM_DYN);

    prep_kernel<<<MDIM + NDIM, 256>>>(x, wq32);
    gemm_kernel<<<dim3(NDIM / 64, MDIM / 64, 1), 256, SMEM_DYN>>>(ws, bias, out);
}